// round 2
// baseline (speedup 1.0000x reference)
#include <cuda_runtime.h>
#include <cstdint>

typedef unsigned long long u64;

// ---------------- folded-parameter block layout (floats) ----------------
// All offsets are multiples of 4 floats (16B) where vector loads need it.
#define OFF_PROTO 0      // 10 x 8
#define OFF_P2    80     // 10 (+2 pad)
#define OFF_A     96     // 2 x 10 x 12 (row-padded 10->12): diag(ln1_g) @ Wv @ Wo
#define OFF_AB    336    // 2 x 12: folded attention bias
#define OFF_W1    360    // 2 x 10 x 64: diag(ln2_g) @ W1
#define OFF_B1    1640   // 2 x 64: b1 + ln2_b @ W1
#define OFF_W2    1768   // 2 x 64 x 12 (row-padded 10->12)
#define OFF_B2    3304   // 2 x 12
#define OFF_WC    3328   // 12
#define OFF_BC    3340   // 1
#define NPAR      3344

__device__ float g_par[NPAR];

// ---------------- packed f32x2 helpers ----------------
__device__ __forceinline__ u64 pk2(float lo, float hi) {
    u64 r; asm("mov.b64 %0,{%1,%2};" : "=l"(r) : "f"(lo), "f"(hi)); return r;
}
__device__ __forceinline__ void upk2(u64 v, float& lo, float& hi) {
    asm("mov.b64 {%0,%1},%2;" : "=f"(lo), "=f"(hi) : "l"(v));
}
__device__ __forceinline__ u64 fma2_(u64 a, u64 b, u64 c) {
    u64 d; asm("fma.rn.f32x2 %0,%1,%2,%3;" : "=l"(d) : "l"(a), "l"(b), "l"(c)); return d;
}

__device__ __forceinline__ float gelu_t(float t) {
    // jax.nn.gelu approximate=True: 0.5*t*(1+tanh(sqrt(2/pi)*(t+0.044715 t^3)))
    float u = t * fmaf(0.03567740814f, t * t, 0.7978845608f);
    float th; asm("tanh.approx.f32 %0,%1;" : "=f"(th) : "f"(u));
    return 0.5f * t * (1.0f + th);
}

// LayerNorm over 10 scalars -> broadcast pairs (n_i, n_i). Affine already folded into weights.
__device__ __forceinline__ void ln10(const float* a, u64* nb) {
    float mu = 0.0f;
#pragma unroll
    for (int i = 0; i < 10; i++) mu += a[i];
    mu *= 0.1f;
    float var = 0.0f;
#pragma unroll
    for (int i = 0; i < 10; i++) { float d = a[i] - mu; var = fmaf(d, d, var); }
    var *= 0.1f;
    float r = rsqrtf(var + 1e-5f);
#pragma unroll
    for (int i = 0; i < 10; i++) { float n = (a[i] - mu) * r; nb[i] = pk2(n, n); }
}

// ---------------- one-time weight folding ----------------
// seq-len==1 => softmax(1x1)==1 => attention output == V. So:
//   seq += LN1(seq) @ (diag(g1) Wv Wo) + (b1ln @ (Wv Wo) + bv @ Wo + bo)
//   t    = LN2(seq) @ (diag(g2) W1)    + (b1 + b2ln @ W1)
__global__ void fold_kernel(
    const float* __restrict__ proto,
    const float* __restrict__ Wv, const float* __restrict__ bv,
    const float* __restrict__ Wo, const float* __restrict__ bo,
    const float* __restrict__ g1, const float* __restrict__ b1ln,
    const float* __restrict__ g2, const float* __restrict__ b2ln,
    const float* __restrict__ W1, const float* __restrict__ b1,
    const float* __restrict__ W2, const float* __restrict__ b2,
    const float* __restrict__ Wc, const float* __restrict__ bc)
{
    int t = threadIdx.x;
    for (int i = t; i < NPAR; i += 256) g_par[i] = 0.0f;
    __syncthreads();

    for (int i = t; i < 80; i += 256) g_par[OFF_PROTO + i] = proto[i];
    if (t < 10) {
        float s = 0.0f;
        for (int d = 0; d < 8; d++) s += proto[t * 8 + d] * proto[t * 8 + d];
        g_par[OFF_P2 + t] = s;
    }
#pragma unroll
    for (int l = 0; l < 2; l++) {
        if (t < 100) {
            int i = t / 10, j = t % 10;
            float m = 0.0f;
            for (int k = 0; k < 10; k++) m += Wv[l * 100 + i * 10 + k] * Wo[l * 100 + k * 10 + j];
            g_par[OFF_A + l * 120 + i * 12 + j] = g1[l * 10 + i] * m;
        }
        if (t < 10) {  // folded attention bias, j = t
            float s = bo[l * 10 + t];
            for (int k = 0; k < 10; k++) s += bv[l * 10 + k] * Wo[l * 100 + k * 10 + t];
            for (int i = 0; i < 10; i++) {
                float m = 0.0f;
                for (int k = 0; k < 10; k++) m += Wv[l * 100 + i * 10 + k] * Wo[l * 100 + k * 10 + t];
                s += b1ln[l * 10 + i] * m;
            }
            g_par[OFF_AB + l * 12 + t] = s;
        }
        for (int e = t; e < 640; e += 256) {
            int i = e / 64;
            g_par[OFF_W1 + l * 640 + e] = g2[l * 10 + i] * W1[l * 640 + e];
        }
        if (t < 64) {
            float s = b1[l * 64 + t];
            for (int i = 0; i < 10; i++) s += b2ln[l * 10 + i] * W1[l * 640 + i * 64 + t];
            g_par[OFF_B1 + l * 64 + t] = s;
        }
        for (int e = t; e < 640; e += 256) {
            int f = e / 10, j = e % 10;
            g_par[OFF_W2 + l * 768 + f * 12 + j] = W2[l * 640 + e];
        }
        if (t < 10) g_par[OFF_B2 + l * 12 + t] = b2[l * 10 + t];
    }
    if (t < 10) g_par[OFF_WC + t] = Wc[t];
    if (t == 0) g_par[OFF_BC] = bc[0];
}

// ---------------- main per-sample kernel ----------------
__global__ void __launch_bounds__(256) fwd_kernel(
    const float* __restrict__ x, float* __restrict__ out, int B)
{
    __shared__ __align__(16) float sm[NPAR];
    for (int i = threadIdx.x; i < NPAR; i += 256) sm[i] = g_par[i];
    __syncthreads();

    int gid = blockIdx.x * 256 + threadIdx.x;
    if (gid >= B) return;

    const float4* xp = reinterpret_cast<const float4*>(x) + gid * 2;
    float4 xa = xp[0], xb = xp[1];
    float x2 = xa.x * xa.x + xa.y * xa.y + xa.z * xa.z + xa.w * xa.w +
               xb.x * xb.x + xb.y * xb.y + xb.z * xb.z + xb.w * xb.w;

    // RBF kernel features: exp(-|x - p_j|^2) = exp(2 x.p - |x|^2 - |p|^2)
    float s[10];
#pragma unroll
    for (int j = 0; j < 10; j++) {
        const float4* pr = reinterpret_cast<const float4*>(&sm[OFF_PROTO + j * 8]);
        float4 p0 = pr[0], p1 = pr[1];
        float dot = xa.x * p0.x + xa.y * p0.y + xa.z * p0.z + xa.w * p0.w +
                    xb.x * p1.x + xb.y * p1.y + xb.z * p1.z + xb.w * p1.w;
        s[j] = __expf(fmaf(2.0f, dot, -x2 - sm[OFF_P2 + j]));
    }

    u64 nb[10];
    u64 acc[5];

#pragma unroll
    for (int l = 0; l < 2; l++) {
        const float* A  = &sm[OFF_A  + l * 120];
        const float* aB = &sm[OFF_AB + l * 12];
        const float* W1 = &sm[OFF_W1 + l * 640];
        const float* b1 = &sm[OFF_B1 + l * 64];
        const float* W2 = &sm[OFF_W2 + l * 768];
        const float* b2 = &sm[OFF_B2 + l * 12];

        // ---- attention block (collapsed to folded 10x10 matvec) ----
        ln10(s, nb);
#pragma unroll
        for (int p = 0; p < 5; p++) acc[p] = *reinterpret_cast<const u64*>(&aB[2 * p]);
#pragma unroll
        for (int i = 0; i < 10; i++) {
            const ulonglong2* ar = reinterpret_cast<const ulonglong2*>(&A[i * 12]);
            ulonglong2 a01 = ar[0];
            ulonglong2 a23 = ar[1];
            u64 a4 = *reinterpret_cast<const u64*>(&A[i * 12 + 8]);
            acc[0] = fma2_(nb[i], a01.x, acc[0]);
            acc[1] = fma2_(nb[i], a01.y, acc[1]);
            acc[2] = fma2_(nb[i], a23.x, acc[2]);
            acc[3] = fma2_(nb[i], a23.y, acc[3]);
            acc[4] = fma2_(nb[i], a4,    acc[4]);
        }
#pragma unroll
        for (int p = 0; p < 5; p++) {
            float a0, a1; upk2(acc[p], a0, a1);
            s[2 * p] += a0; s[2 * p + 1] += a1;
        }

        // ---- FFN block ----
        ln10(s, nb);
#pragma unroll
        for (int p = 0; p < 5; p++) acc[p] = *reinterpret_cast<const u64*>(&b2[2 * p]);
#pragma unroll 1
        for (int f = 0; f < 64; f += 4) {
            u64 t01 = *reinterpret_cast<const u64*>(&b1[f]);
            u64 t23 = *reinterpret_cast<const u64*>(&b1[f + 2]);
#pragma unroll
            for (int i = 0; i < 10; i++) {
                ulonglong2 w = *reinterpret_cast<const ulonglong2*>(&W1[i * 64 + f]);
                t01 = fma2_(nb[i], w.x, t01);
                t23 = fma2_(nb[i], w.y, t23);
            }
            float t0, t1, t2, t3;
            upk2(t01, t0, t1); upk2(t23, t2, t3);
            float gls[4];
            gls[0] = gelu_t(t0); gls[1] = gelu_t(t1);
            gls[2] = gelu_t(t2); gls[3] = gelu_t(t3);
#pragma unroll
            for (int fi = 0; fi < 4; fi++) {
                u64 gg = pk2(gls[fi], gls[fi]);
                const ulonglong2* wr = reinterpret_cast<const ulonglong2*>(&W2[(f + fi) * 12]);
                ulonglong2 w01 = wr[0];
                ulonglong2 w23 = wr[1];
                u64 w4 = *reinterpret_cast<const u64*>(&W2[(f + fi) * 12 + 8]);
                acc[0] = fma2_(gg, w01.x, acc[0]);
                acc[1] = fma2_(gg, w01.y, acc[1]);
                acc[2] = fma2_(gg, w23.x, acc[2]);
                acc[3] = fma2_(gg, w23.y, acc[3]);
                acc[4] = fma2_(gg, w4,    acc[4]);
            }
        }
#pragma unroll
        for (int p = 0; p < 5; p++) {
            float a0, a1; upk2(acc[p], a0, a1);
            s[2 * p] += a0; s[2 * p + 1] += a1;
        }
    }

    float logit = sm[OFF_BC];
#pragma unroll
    for (int j = 0; j < 10; j++) logit = fmaf(s[j], sm[OFF_WC + j], logit);
    out[gid] = 1.0f / (1.0f + __expf(-logit));
}

// ---------------- launch ----------------
extern "C" void kernel_launch(void* const* d_in, const int* in_sizes, int n_in,
                              void* d_out, int out_size)
{
    const float* x = (const float*)d_in[0];
    int B = in_sizes[0] / 8;

    // input order: x, prototypes, Wq, bq, Wk, bk, Wv, bv, Wo, bo,
    //              ln1_g, ln1_b, ln2_g, ln2_b, W1, b1, W2, b2, Wc, bc
    fold_kernel<<<1, 256>>>(
        (const float*)d_in[1],                           // prototypes
        (const float*)d_in[6],  (const float*)d_in[7],   // Wv, bv
        (const float*)d_in[8],  (const float*)d_in[9],   // Wo, bo
        (const float*)d_in[10], (const float*)d_in[11],  // ln1_g, ln1_b
        (const float*)d_in[12], (const float*)d_in[13],  // ln2_g, ln2_b
        (const float*)d_in[14], (const float*)d_in[15],  // W1, b1
        (const float*)d_in[16], (const float*)d_in[17],  // W2, b2
        (const float*)d_in[18], (const float*)d_in[19]); // Wc, bc

    fwd_kernel<<<(B + 255) / 256, 256>>>(x, (float*)d_out, B);
}